// round 15
// baseline (speedup 1.0000x reference)
#include <cuda_runtime.h>
#include <cuda_bf16.h>
#include <cstdint>
#include <math.h>

#define NN   50000
#define NE   800000
#define ET   850000   // NE + NN self loops
#define IND  256
#define HID  128
#define NG   64
#define NEG_SLOPE 0.2f
#define SCAN_B ((NN + 255) / 256)   // 196
#define FILL_B ((ET + 255) / 256)   // 3321
#define GEMM_B ((NN + 127) / 128)   // 391

// ---------------- scratch (no allocations allowed; statics start zeroed) ----------------
__device__ float          g_bufA[NN * HID];   // fp32 attn<0> output / gemm2 input
__device__ __nv_bfloat16  g_hb[NN * HID];     // bf16 h for gathering (12.8 MB)
__device__ float g_as[NN];
__device__ float g_ad[NN];
__device__ float g_w[ET];
__device__ int   g_batch[NN];
__device__ int   g_counts[NN];   // reset by fill body each run (static zero first run)
__device__ int   g_roff[NN + 1];
__device__ int   g_cursor[NN];
__device__ int   g_csr[ET];
__device__ float g_pool[NG * HID];  // reset by head each run
__device__ int   g_gcnt[NG];        // reset by head each run

// ---------------- block-local dtype sniffing (256-thread blocks) ----------------
__device__ __forceinline__ int detect_e64(const unsigned* e) {
    __shared__ int sf;
    if (threadIdx.x == 0) sf = 0;
    __syncthreads();
    if (e[2 * threadIdx.x + 1] != 0u) atomicOr(&sf, 1);
    __syncthreads();
    return !sf;
}
__device__ __forceinline__ int detect_b64(const unsigned* b) {
    __shared__ int sf;
    if (threadIdx.x == 0) sf = 0;
    __syncthreads();
    if (b[NN - 1 - 2 * threadIdx.x] != 0u) atomicOr(&sf, 1);
    __syncthreads();
    return !sf;
}

// ---------------- histogram over dst + batch decode ----------------
__global__ void hist_kernel(const void* __restrict__ edge,
                            const void* __restrict__ batch) {
    int e64 = detect_e64((const unsigned*)edge);
    int b64 = detect_b64((const unsigned*)batch);
    int i = blockIdx.x * blockDim.x + threadIdx.x;
    if (i < NE) {
        int d = e64 ? (int)((const long long*)edge)[NE + i]
                    : ((const int*)edge)[NE + i];
        atomicAdd(&g_counts[d], 1);
    }
    if (i < NN) {
        int b = b64 ? (int)((const long long*)batch)[i]
                    : ((const int*)batch)[i];
        g_batch[i] = b;
        atomicAdd(&g_gcnt[b], 1);
    }
}

// ---------------- one-kernel scan: block reduces its full prefix + local scan ----------------
__global__ void scan_kernel() {
    __shared__ int ssum[8];
    __shared__ int ws[8];
    int t = threadIdx.x, bid = blockIdx.x;
    int lane = t & 31, wrp = t >> 5;
    int base = bid * 256;

    // prefix: sum counts[0..base) (coalesced strided)
    int pre = 0;
    for (int j = t; j < base; j += 256) pre += g_counts[j];
#pragma unroll
    for (int o = 16; o; o >>= 1) pre += __shfl_xor_sync(0xffffffffu, pre, o);
    if (lane == 0) ssum[wrp] = pre;
    __syncthreads();
    if (t == 0) {
        int s = 0;
#pragma unroll
        for (int j = 0; j < 8; j++) s += ssum[j];
        ssum[0] = s + base;          // + base self-loops of preceding elements
    }
    __syncthreads();
    int off = ssum[0];

    // local exclusive scan of (counts[i]+1)
    int i = base + t;
    int v = (i < NN) ? g_counts[i] + 1 : 0;
    int incl = v;
#pragma unroll
    for (int o = 1; o < 32; o <<= 1) {
        int x = __shfl_up_sync(0xffffffffu, incl, o);
        if (lane >= o) incl += x;
    }
    if (lane == 31) ws[wrp] = incl;
    __syncthreads();
    if (t < 8) {
        int s = ws[t];
        int inc2 = s;
#pragma unroll
        for (int o = 1; o < 8; o <<= 1) {
            int x = __shfl_up_sync(0xffu, inc2, o);
            if (t >= o) inc2 += x;
        }
        ws[t] = inc2 - s;
    }
    __syncthreads();
    if (i == 0) g_roff[NN] = ET;
    if (i < NN) {
        int r = off + ws[wrp] + incl - v;
        g_roff[i] = r;
        g_cursor[i] = r;
    }
}

// ================= bf16 mma.sync helpers =================
__device__ __forceinline__ uint32_t smem_u32(const void* p) {
    uint32_t a;
    asm("{ .reg .u64 t; cvta.to.shared.u64 t, %1; cvt.u32.u64 %0, t; }"
        : "=r"(a) : "l"(p));
    return a;
}

#define LDM_X4(r0, r1, r2, r3, addr) \
    asm volatile("ldmatrix.sync.aligned.m8n8.x4.shared.b16 {%0,%1,%2,%3}, [%4];" \
        : "=r"(r0), "=r"(r1), "=r"(r2), "=r"(r3) : "r"(addr))
#define LDM_X4T(r0, r1, r2, r3, addr) \
    asm volatile("ldmatrix.sync.aligned.m8n8.x4.trans.shared.b16 {%0,%1,%2,%3}, [%4];" \
        : "=r"(r0), "=r"(r1), "=r"(r2), "=r"(r3) : "r"(addr))
#define MMA16816(c, a0, a1, a2, a3, b0, b1) \
    asm volatile("mma.sync.aligned.m16n8k16.row.col.f32.bf16.bf16.f32 " \
        "{%0,%1,%2,%3}, {%4,%5,%6,%7}, {%8,%9}, {%0,%1,%2,%3};" \
        : "+f"((c)[0]), "+f"((c)[1]), "+f"((c)[2]), "+f"((c)[3]) \
        : "r"(a0), "r"(a1), "r"(a2), "r"(a3), "r"(b0), "r"(b1))

// GEMM body: C[M,128](bf16) = A[M,K](fp32->bf16) @ W[K,128](fp32->bf16)
// + fused alpha-dot epilogue. Called with a tile id.
template <int K>
__device__ __forceinline__ void gemm_body(
    int bid, char* smem,
    const float* __restrict__ A, const float* __restrict__ W,
    __nv_bfloat16* __restrict__ C, int M,
    const float* __restrict__ asrc, const float* __restrict__ adst) {
    constexpr int KC = 128;
    constexpr int LD = 136;
    __nv_bfloat16* sA = (__nv_bfloat16*)smem;                    // 128 x LD
    __nv_bfloat16* sW = (__nv_bfloat16*)(smem + 128 * LD * 2);   // KC x LD

    int tid = threadIdx.x;
    int wid = tid >> 5, lane = tid & 31;
    int m0 = bid * 128;

    const int wm = (wid & 3) * 32;
    const int wn = (wid >> 2) * 64;
    int gq = lane >> 2, tg = lane & 3;

    float acc[2][8][4];
#pragma unroll
    for (int mt = 0; mt < 2; mt++)
#pragma unroll
        for (int nt = 0; nt < 8; nt++)
#pragma unroll
            for (int j = 0; j < 4; j++) acc[mt][nt][j] = 0.f;

    uint32_t sAu = smem_u32(sA);
    uint32_t sWu = smem_u32(sW);

    for (int kc = 0; kc < K; kc += KC) {
        for (int idx = tid; idx < 128 * KC / 8; idx += 256) {
            int row = idx >> 4;
            int kv  = (idx & 15) * 8;
            int gm  = m0 + row;
            float4 f0 = make_float4(0.f, 0.f, 0.f, 0.f), f1 = f0;
            if (gm < M) {
                f0 = *(const float4*)(A + (size_t)gm * K + kc + kv);
                f1 = *(const float4*)(A + (size_t)gm * K + kc + kv + 4);
            }
            __nv_bfloat162 p0 = __floats2bfloat162_rn(f0.x, f0.y);
            __nv_bfloat162 p1 = __floats2bfloat162_rn(f0.z, f0.w);
            __nv_bfloat162 p2 = __floats2bfloat162_rn(f1.x, f1.y);
            __nv_bfloat162 p3 = __floats2bfloat162_rn(f1.z, f1.w);
            uint4 pk;
            pk.x = *(unsigned*)&p0; pk.y = *(unsigned*)&p1;
            pk.z = *(unsigned*)&p2; pk.w = *(unsigned*)&p3;
            *(uint4*)(sA + row * LD + kv) = pk;
        }
        for (int idx = tid; idx < KC * HID / 8; idx += 256) {
            int k = idx >> 4;
            int n = (idx & 15) * 8;
            float4 f0 = *(const float4*)(W + (size_t)(kc + k) * HID + n);
            float4 f1 = *(const float4*)(W + (size_t)(kc + k) * HID + n + 4);
            __nv_bfloat162 p0 = __floats2bfloat162_rn(f0.x, f0.y);
            __nv_bfloat162 p1 = __floats2bfloat162_rn(f0.z, f0.w);
            __nv_bfloat162 p2 = __floats2bfloat162_rn(f1.x, f1.y);
            __nv_bfloat162 p3 = __floats2bfloat162_rn(f1.z, f1.w);
            uint4 pk;
            pk.x = *(unsigned*)&p0; pk.y = *(unsigned*)&p1;
            pk.z = *(unsigned*)&p2; pk.w = *(unsigned*)&p3;
            *(uint4*)(sW + k * LD + n) = pk;
        }
        __syncthreads();

#pragma unroll
        for (int ks = 0; ks < KC / 16; ks++) {
            int k = ks * 16;
            uint32_t a[2][4];
#pragma unroll
            for (int mt = 0; mt < 2; mt++) {
                uint32_t addr = sAu +
                    ((wm + mt * 16 + (lane & 15)) * LD + k + (lane >> 4) * 8) * 2;
                LDM_X4(a[mt][0], a[mt][1], a[mt][2], a[mt][3], addr);
            }
            uint32_t b[8][2];
#pragma unroll
            for (int np = 0; np < 4; np++) {
                uint32_t addr = sWu +
                    ((k + (lane & 15)) * LD + wn + np * 16 + (lane >> 4) * 8) * 2;
                uint32_t r0, r1, r2, r3;
                LDM_X4T(r0, r1, r2, r3, addr);
                b[np * 2][0] = r0;     b[np * 2][1] = r1;
                b[np * 2 + 1][0] = r2; b[np * 2 + 1][1] = r3;
            }
#pragma unroll
            for (int mt = 0; mt < 2; mt++)
#pragma unroll
                for (int nt = 0; nt < 8; nt++)
                    MMA16816(acc[mt][nt], a[mt][0], a[mt][1], a[mt][2], a[mt][3],
                             b[nt][0], b[nt][1]);
        }
        __syncthreads();
    }

    // epilogue 1: bf16 stores of h
#pragma unroll
    for (int mt = 0; mt < 2; mt++) {
        int r0 = m0 + wm + mt * 16 + gq;
        int r1 = r0 + 8;
#pragma unroll
        for (int nt = 0; nt < 8; nt++) {
            int c = wn + nt * 8 + tg * 2;
            if (r0 < M) {
                __nv_bfloat162 p = __floats2bfloat162_rn(acc[mt][nt][0], acc[mt][nt][1]);
                *(unsigned*)(C + (size_t)r0 * HID + c) = *(unsigned*)&p;
            }
            if (r1 < M) {
                __nv_bfloat162 p = __floats2bfloat162_rn(acc[mt][nt][2], acc[mt][nt][3]);
                *(unsigned*)(C + (size_t)r1 * HID + c) = *(unsigned*)&p;
            }
        }
    }

    // epilogue 2: fused alpha dots
    float* sal = (float*)smem;
    int nh = wid >> 2;
#pragma unroll
    for (int mt = 0; mt < 2; mt++) {
        float s0 = 0.f, d0 = 0.f, s1 = 0.f, d1 = 0.f;
#pragma unroll
        for (int nt = 0; nt < 8; nt++) {
            int c = wn + nt * 8 + tg * 2;
            float a0 = __ldg(&asrc[c]), a1 = __ldg(&asrc[c + 1]);
            float e0 = __ldg(&adst[c]), e1 = __ldg(&adst[c + 1]);
            s0 += acc[mt][nt][0] * a0 + acc[mt][nt][1] * a1;
            d0 += acc[mt][nt][0] * e0 + acc[mt][nt][1] * e1;
            s1 += acc[mt][nt][2] * a0 + acc[mt][nt][3] * a1;
            d1 += acc[mt][nt][2] * e0 + acc[mt][nt][3] * e1;
        }
#pragma unroll
        for (int o = 1; o <= 2; o <<= 1) {
            s0 += __shfl_xor_sync(0xffffffffu, s0, o);
            d0 += __shfl_xor_sync(0xffffffffu, d0, o);
            s1 += __shfl_xor_sync(0xffffffffu, s1, o);
            d1 += __shfl_xor_sync(0xffffffffu, d1, o);
        }
        if (tg == 0) {
            int row0 = wm + mt * 16 + gq, row1 = row0 + 8;
            sal[(row0 * 2 + nh) * 2 + 0] = s0;
            sal[(row0 * 2 + nh) * 2 + 1] = d0;
            sal[(row1 * 2 + nh) * 2 + 0] = s1;
            sal[(row1 * 2 + nh) * 2 + 1] = d1;
        }
    }
    __syncthreads();
    if (tid < 128) {
        int m = m0 + tid;
        if (m < M) {
            g_as[m] = sal[(tid * 2 + 0) * 2 + 0] + sal[(tid * 2 + 1) * 2 + 0];
            g_ad[m] = sal[(tid * 2 + 0) * 2 + 1] + sal[(tid * 2 + 1) * 2 + 1];
        }
    }
}

// ---------------- fused fill + gemm1 (independent work, blockIdx split) ----------------
__global__ void __launch_bounds__(256, 2)
fillgemm_kernel(const void* __restrict__ edge,
                const float* __restrict__ A, const float* __restrict__ W,
                __nv_bfloat16* __restrict__ C, int M,
                const float* __restrict__ asrc, const float* __restrict__ adst) {
    extern __shared__ char smem[];
    if (blockIdx.x < GEMM_B) {
        gemm_body<IND>(blockIdx.x, smem, A, W, C, M, asrc, adst);
    } else {
        int fb = blockIdx.x - GEMM_B;
        int e64 = detect_e64((const unsigned*)edge);
        int i = fb * 256 + threadIdx.x;
        if (i < NN) g_counts[i] = 0;         // reset for next replay (post-scan)
        if (i >= ET) return;
        int s, d;
        if (i < NE) {
            if (e64) {
                s = (int)((const long long*)edge)[i];
                d = (int)((const long long*)edge)[NE + i];
            } else {
                s = ((const int*)edge)[i];
                d = ((const int*)edge)[NE + i];
            }
        } else {
            s = d = i - NE;
        }
        int p = atomicAdd(&g_cursor[d], 1);
        g_csr[p] = s;
    }
}

// ---------------- standalone gemm2 ----------------
__global__ void __launch_bounds__(256, 2)
gemm2_kernel(const float* __restrict__ A, const float* __restrict__ W,
             __nv_bfloat16* __restrict__ C, int M,
             const float* __restrict__ asrc, const float* __restrict__ adst) {
    extern __shared__ char smem[];
    gemm_body<HID>(blockIdx.x, smem, A, W, C, M, asrc, adst);
}

// ---------------- fused attention: warp per dst, bf16 gathers (champion structure) ----------------
template <int POOL>
__global__ void __launch_bounds__(256)
attn_kernel(const __nv_bfloat16* __restrict__ h, const float* __restrict__ bias,
            float* __restrict__ out) {
    int d = blockIdx.x * 8 + (threadIdx.x >> 5);
    if (d >= NN) return;
    int lane = threadIdx.x & 31;
    int beg = g_roff[d], end = g_roff[d + 1];
    float add = g_ad[d];

    float den = 0.f;
    for (int i = beg + lane; i < end; i += 32) {
        float e = __ldg(&g_as[g_csr[i]]) + add;
        e = e > 0.f ? e : NEG_SLOPE * e;
        float w = __expf(e);
        g_w[i] = w;
        den += w;
    }
#pragma unroll
    for (int o = 16; o; o >>= 1) den += __shfl_xor_sync(0xffffffffu, den, o);
    float inv = 1.f / den;
    __syncwarp();

    float4 acc = make_float4(0.f, 0.f, 0.f, 0.f);
    int i = beg;
    for (; i + 4 <= end; i += 4) {
        int   s0 = g_csr[i],     s1 = g_csr[i + 1];
        int   s2 = g_csr[i + 2], s3 = g_csr[i + 3];
        float c0 = g_w[i] * inv,     c1 = g_w[i + 1] * inv;
        float c2 = g_w[i + 2] * inv, c3 = g_w[i + 3] * inv;
        uint2 v0 = __ldg(&((const uint2*)(h + (size_t)s0 * HID))[lane]);
        uint2 v1 = __ldg(&((const uint2*)(h + (size_t)s1 * HID))[lane]);
        uint2 v2 = __ldg(&((const uint2*)(h + (size_t)s2 * HID))[lane]);
        uint2 v3 = __ldg(&((const uint2*)(h + (size_t)s3 * HID))[lane]);
        float2 a0 = __bfloat1622float2(*(__nv_bfloat162*)&v0.x);
        float2 b0 = __bfloat1622float2(*(__nv_bfloat162*)&v0.y);
        float2 a1 = __bfloat1622float2(*(__nv_bfloat162*)&v1.x);
        float2 b1 = __bfloat1622float2(*(__nv_bfloat162*)&v1.y);
        float2 a2 = __bfloat1622float2(*(__nv_bfloat162*)&v2.x);
        float2 b2 = __bfloat1622float2(*(__nv_bfloat162*)&v2.y);
        float2 a3 = __bfloat1622float2(*(__nv_bfloat162*)&v3.x);
        float2 b3 = __bfloat1622float2(*(__nv_bfloat162*)&v3.y);
        acc.x += c0 * a0.x + c1 * a1.x + c2 * a2.x + c3 * a3.x;
        acc.y += c0 * a0.y + c1 * a1.y + c2 * a2.y + c3 * a3.y;
        acc.z += c0 * b0.x + c1 * b1.x + c2 * b2.x + c3 * b3.x;
        acc.w += c0 * b0.y + c1 * b1.y + c2 * b2.y + c3 * b3.y;
    }
    for (; i < end; i++) {
        int s = g_csr[i];
        float c = g_w[i] * inv;
        uint2 v = __ldg(&((const uint2*)(h + (size_t)s * HID))[lane]);
        float2 a = __bfloat1622float2(*(__nv_bfloat162*)&v.x);
        float2 b = __bfloat1622float2(*(__nv_bfloat162*)&v.y);
        acc.x += c * a.x; acc.y += c * a.y;
        acc.z += c * b.x; acc.w += c * b.y;
    }

    float4 bb = ((const float4*)bias)[lane];
    acc.x = fmaxf(acc.x + bb.x, 0.f);
    acc.y = fmaxf(acc.y + bb.y, 0.f);
    acc.z = fmaxf(acc.z + bb.z, 0.f);
    acc.w = fmaxf(acc.w + bb.w, 0.f);

    if (POOL) {
        int g = g_batch[d];
        float* p = g_pool + g * HID + lane * 4;
        atomicAdd(p + 0, acc.x);
        atomicAdd(p + 1, acc.y);
        atomicAdd(p + 2, acc.z);
        atomicAdd(p + 3, acc.w);
    } else {
        ((float4*)(out + (size_t)d * HID))[lane] = acc;
    }
}

// ---------------- classifier head (also re-zeroes pool/gcnt for next replay) ----------------
__global__ void head_kernel(const float* __restrict__ Wc,
                            const float* __restrict__ bc,
                            float* __restrict__ out) {
    __shared__ float ssum[4];
    int g = blockIdx.x;
    int t = threadIdx.x;         // 128 threads
    int lane = t & 31, wrp = t >> 5;
    float s = g_pool[g * HID + t] * __ldg(&Wc[t]);
#pragma unroll
    for (int o = 16; o; o >>= 1) s += __shfl_xor_sync(0xffffffffu, s, o);
    if (lane == 0) ssum[wrp] = s;
    __syncthreads();
    if (t == 0) {
        float tot = ssum[0] + ssum[1] + ssum[2] + ssum[3];
        float c = fmaxf((float)g_gcnt[g], 1.f);
        float v = tot / c + bc[0];
        out[g] = 1.f / (1.f + expf(-v));
    }
    g_pool[g * HID + t] = 0.f;
    if (t == 0) g_gcnt[g] = 0;
}

// ---------------- launch ----------------
extern "C" void kernel_launch(void* const* d_in, const int* in_sizes, int n_in,
                              void* d_out, int out_size) {
    const float* x    = (const float*)d_in[0];
    const void*  edge = d_in[1];
    const void*  batch= d_in[2];
    const float* W1   = (const float*)d_in[3];
    const float* as1  = (const float*)d_in[4];
    const float* ad1  = (const float*)d_in[5];
    const float* b1   = (const float*)d_in[6];
    const float* W2   = (const float*)d_in[7];
    const float* as2  = (const float*)d_in[8];
    const float* ad2  = (const float*)d_in[9];
    const float* b2   = (const float*)d_in[10];
    const float* Wc   = (const float*)d_in[11];
    const float* bc   = (const float*)d_in[12];
    float* out = (float*)d_out;
    (void)in_sizes; (void)n_in; (void)out_size;

    float* bufA; cudaGetSymbolAddress((void**)&bufA, g_bufA);
    __nv_bfloat16* hb; cudaGetSymbolAddress((void**)&hb, g_hb);

    const int HB = (NE + 255) / 256;
    const int WB = (NN + 7) / 8;

    const int SMEM = 2 * 128 * 136 * 2;   // 69632
    cudaFuncSetAttribute(fillgemm_kernel,
                         cudaFuncAttributeMaxDynamicSharedMemorySize, SMEM);
    cudaFuncSetAttribute(gemm2_kernel,
                         cudaFuncAttributeMaxDynamicSharedMemorySize, SMEM);

    hist_kernel<<<HB, 256>>>(edge, batch);                                   // 1
    scan_kernel<<<SCAN_B, 256>>>();                                          // 2
    fillgemm_kernel<<<GEMM_B + FILL_B, 256, SMEM>>>(edge, x, W1, hb, NN,
                                                    as1, ad1);               // 3
    attn_kernel<0><<<WB, 256>>>(hb, b1, bufA);                               // 4 (profiled)
    gemm2_kernel<<<GEMM_B, 256, SMEM>>>(bufA, W2, hb, NN, as2, ad2);         // 5
    attn_kernel<1><<<WB, 256>>>(hb, b2, nullptr);                            // 6
    head_kernel<<<NG, 128>>>(Wc, bc, out);                                   // 7
}

// round 16
// speedup vs baseline: 1.7399x; 1.7399x over previous
#include <cuda_runtime.h>
#include <cuda_bf16.h>
#include <cstdint>
#include <math.h>

#define NN   50000
#define NE   800000
#define ET   850000   // NE + NN self loops
#define IND  256
#define HID  128
#define NG   64
#define NEG_SLOPE 0.2f
#define SCAN_B ((NN + 255) / 256)   // 196
#define FILL_B ((ET + 255) / 256)   // 3321
#define GEMM_B ((NN + 127) / 128)   // 391

// ---------------- scratch (no allocations allowed; statics start zeroed) ----------------
__device__ __nv_bfloat16  g_hb[NN * HID];     // bf16 h (gemm output)
__device__ __nv_bfloat16  g_hb2[NN * HID];    // bf16 attn<0> output -> gemm2 input
__device__ float g_as[NN];
__device__ float g_ad[NN];
__device__ float g_w[ET];
__device__ int   g_batch[NN];
__device__ int   g_counts[NN];   // reset in fill body each run (static zero first run)
__device__ int   g_roff[NN + 1];
__device__ int   g_cursor[NN];
__device__ int   g_csr[ET];
__device__ float g_pool[NG * HID];  // reset by head each run
__device__ int   g_gcnt[NG];        // reset by head each run

// ---------------- block-local dtype sniffing (256-thread blocks) ----------------
__device__ __forceinline__ int detect_e64(const unsigned* e) {
    __shared__ int sf;
    if (threadIdx.x == 0) sf = 0;
    __syncthreads();
    if (e[2 * threadIdx.x + 1] != 0u) atomicOr(&sf, 1);
    __syncthreads();
    return !sf;
}
__device__ __forceinline__ int detect_b64(const unsigned* b) {
    __shared__ int sf;
    if (threadIdx.x == 0) sf = 0;
    __syncthreads();
    if (b[NN - 1 - 2 * threadIdx.x] != 0u) atomicOr(&sf, 1);
    __syncthreads();
    return !sf;
}

// ---------------- histogram over dst + batch decode ----------------
__global__ void hist_kernel(const void* __restrict__ edge,
                            const void* __restrict__ batch) {
    int e64 = detect_e64((const unsigned*)edge);
    int b64 = detect_b64((const unsigned*)batch);
    int i = blockIdx.x * blockDim.x + threadIdx.x;
    if (i < NE) {
        int d = e64 ? (int)((const long long*)edge)[NE + i]
                    : ((const int*)edge)[NE + i];
        atomicAdd(&g_counts[d], 1);
    }
    if (i < NN) {
        int b = b64 ? (int)((const long long*)batch)[i]
                    : ((const int*)batch)[i];
        g_batch[i] = b;
        atomicAdd(&g_gcnt[b], 1);
    }
}

// ---------------- one-kernel scan: block reduces its full prefix + local scan ----------------
__global__ void scan_kernel() {
    __shared__ int ssum[8];
    __shared__ int ws[8];
    int t = threadIdx.x, bid = blockIdx.x;
    int lane = t & 31, wrp = t >> 5;
    int base = bid * 256;

    int pre = 0;
    for (int j = t; j < base; j += 256) pre += g_counts[j];
#pragma unroll
    for (int o = 16; o; o >>= 1) pre += __shfl_xor_sync(0xffffffffu, pre, o);
    if (lane == 0) ssum[wrp] = pre;
    __syncthreads();
    if (t == 0) {
        int s = 0;
#pragma unroll
        for (int j = 0; j < 8; j++) s += ssum[j];
        ssum[0] = s + base;          // + base self-loops of preceding elements
    }
    __syncthreads();
    int off = ssum[0];

    int i = base + t;
    int v = (i < NN) ? g_counts[i] + 1 : 0;
    int incl = v;
#pragma unroll
    for (int o = 1; o < 32; o <<= 1) {
        int x = __shfl_up_sync(0xffffffffu, incl, o);
        if (lane >= o) incl += x;
    }
    if (lane == 31) ws[wrp] = incl;
    __syncthreads();
    if (t < 8) {
        int s = ws[t];
        int inc2 = s;
#pragma unroll
        for (int o = 1; o < 8; o <<= 1) {
            int x = __shfl_up_sync(0xffu, inc2, o);
            if (t >= o) inc2 += x;
        }
        ws[t] = inc2 - s;
    }
    __syncthreads();
    if (i == 0) g_roff[NN] = ET;
    if (i < NN) {
        int r = off + ws[wrp] + incl - v;
        g_roff[i] = r;
        g_cursor[i] = r;
    }
}

// ---------------- CSR fill (also resets counts for next replay) ----------------
__global__ void fill_kernel(const void* __restrict__ edge) {
    int e64 = detect_e64((const unsigned*)edge);
    int i = blockIdx.x * blockDim.x + threadIdx.x;
    if (i < NN) g_counts[i] = 0;
    if (i >= ET) return;
    int s, d;
    if (i < NE) {
        if (e64) {
            s = (int)((const long long*)edge)[i];
            d = (int)((const long long*)edge)[NE + i];
        } else {
            s = ((const int*)edge)[i];
            d = ((const int*)edge)[NE + i];
        }
    } else {
        s = d = i - NE;
    }
    int p = atomicAdd(&g_cursor[d], 1);
    g_csr[p] = s;
}

// ================= bf16 mma.sync helpers =================
__device__ __forceinline__ uint32_t smem_u32(const void* p) {
    uint32_t a;
    asm("{ .reg .u64 t; cvta.to.shared.u64 t, %1; cvt.u32.u64 %0, t; }"
        : "=r"(a) : "l"(p));
    return a;
}

#define LDM_X4(r0, r1, r2, r3, addr) \
    asm volatile("ldmatrix.sync.aligned.m8n8.x4.shared.b16 {%0,%1,%2,%3}, [%4];" \
        : "=r"(r0), "=r"(r1), "=r"(r2), "=r"(r3) : "r"(addr))
#define LDM_X4T(r0, r1, r2, r3, addr) \
    asm volatile("ldmatrix.sync.aligned.m8n8.x4.trans.shared.b16 {%0,%1,%2,%3}, [%4];" \
        : "=r"(r0), "=r"(r1), "=r"(r2), "=r"(r3) : "r"(addr))
#define MMA16816(c, a0, a1, a2, a3, b0, b1) \
    asm volatile("mma.sync.aligned.m16n8k16.row.col.f32.bf16.bf16.f32 " \
        "{%0,%1,%2,%3}, {%4,%5,%6,%7}, {%8,%9}, {%0,%1,%2,%3};" \
        : "+f"((c)[0]), "+f"((c)[1]), "+f"((c)[2]), "+f"((c)[3]) \
        : "r"(a0), "r"(a1), "r"(a2), "r"(a3), "r"(b0), "r"(b1))

template <int K, typename TA>
__device__ __forceinline__ void gemm_body(
    int bid, char* smem,
    const TA* __restrict__ A, const float* __restrict__ W,
    __nv_bfloat16* __restrict__ C, int M,
    const float* __restrict__ asrc, const float* __restrict__ adst) {
    constexpr int KC = 128;
    constexpr int LD = 136;
    __nv_bfloat16* sA = (__nv_bfloat16*)smem;
    __nv_bfloat16* sW = (__nv_bfloat16*)(smem + 128 * LD * 2);

    int tid = threadIdx.x;
    int wid = tid >> 5, lane = tid & 31;
    int m0 = bid * 128;

    const int wm = (wid & 3) * 32;
    const int wn = (wid >> 2) * 64;
    int gq = lane >> 2, tg = lane & 3;

    float acc[2][8][4];
#pragma unroll
    for (int mt = 0; mt < 2; mt++)
#pragma unroll
        for (int nt = 0; nt < 8; nt++)
#pragma unroll
            for (int j = 0; j < 4; j++) acc[mt][nt][j] = 0.f;

    uint32_t sAu = smem_u32(sA);
    uint32_t sWu = smem_u32(sW);

    for (int kc = 0; kc < K; kc += KC) {
        for (int idx = tid; idx < 128 * KC / 8; idx += 256) {
            int row = idx >> 4;
            int kv  = (idx & 15) * 8;
            int gm  = m0 + row;
            uint4 pk = make_uint4(0, 0, 0, 0);
            if (sizeof(TA) == 4) {
                const float* Af = (const float*)A;
                if (gm < M) {
                    float4 f0 = *(const float4*)(Af + (size_t)gm * K + kc + kv);
                    float4 f1 = *(const float4*)(Af + (size_t)gm * K + kc + kv + 4);
                    __nv_bfloat162 p0 = __floats2bfloat162_rn(f0.x, f0.y);
                    __nv_bfloat162 p1 = __floats2bfloat162_rn(f0.z, f0.w);
                    __nv_bfloat162 p2 = __floats2bfloat162_rn(f1.x, f1.y);
                    __nv_bfloat162 p3 = __floats2bfloat162_rn(f1.z, f1.w);
                    pk.x = *(unsigned*)&p0; pk.y = *(unsigned*)&p1;
                    pk.z = *(unsigned*)&p2; pk.w = *(unsigned*)&p3;
                }
            } else {
                const __nv_bfloat16* Ab = (const __nv_bfloat16*)A;
                if (gm < M)
                    pk = *(const uint4*)(Ab + (size_t)gm * K + kc + kv);
            }
            *(uint4*)(sA + row * LD + kv) = pk;
        }
        for (int idx = tid; idx < KC * HID / 8; idx += 256) {
            int k = idx >> 4;
            int n = (idx & 15) * 8;
            float4 f0 = *(const float4*)(W + (size_t)(kc + k) * HID + n);
            float4 f1 = *(const float4*)(W + (size_t)(kc + k) * HID + n + 4);
            __nv_bfloat162 p0 = __floats2bfloat162_rn(f0.x, f0.y);
            __nv_bfloat162 p1 = __floats2bfloat162_rn(f0.z, f0.w);
            __nv_bfloat162 p2 = __floats2bfloat162_rn(f1.x, f1.y);
            __nv_bfloat162 p3 = __floats2bfloat162_rn(f1.z, f1.w);
            uint4 pk;
            pk.x = *(unsigned*)&p0; pk.y = *(unsigned*)&p1;
            pk.z = *(unsigned*)&p2; pk.w = *(unsigned*)&p3;
            *(uint4*)(sW + k * LD + n) = pk;
        }
        __syncthreads();

#pragma unroll
        for (int ks = 0; ks < KC / 16; ks++) {
            int k = ks * 16;
            uint32_t a[2][4];
#pragma unroll
            for (int mt = 0; mt < 2; mt++) {
                uint32_t addr = sAu +
                    ((wm + mt * 16 + (lane & 15)) * LD + k + (lane >> 4) * 8) * 2;
                LDM_X4(a[mt][0], a[mt][1], a[mt][2], a[mt][3], addr);
            }
            uint32_t b[8][2];
#pragma unroll
            for (int np = 0; np < 4; np++) {
                uint32_t addr = sWu +
                    ((k + (lane & 15)) * LD + wn + np * 16 + (lane >> 4) * 8) * 2;
                uint32_t r0, r1, r2, r3;
                LDM_X4T(r0, r1, r2, r3, addr);
                b[np * 2][0] = r0;     b[np * 2][1] = r1;
                b[np * 2 + 1][0] = r2; b[np * 2 + 1][1] = r3;
            }
#pragma unroll
            for (int mt = 0; mt < 2; mt++)
#pragma unroll
                for (int nt = 0; nt < 8; nt++)
                    MMA16816(acc[mt][nt], a[mt][0], a[mt][1], a[mt][2], a[mt][3],
                             b[nt][0], b[nt][1]);
        }
        __syncthreads();
    }

#pragma unroll
    for (int mt = 0; mt < 2; mt++) {
        int r0 = m0 + wm + mt * 16 + gq;
        int r1 = r0 + 8;
#pragma unroll
        for (int nt = 0; nt < 8; nt++) {
            int c = wn + nt * 8 + tg * 2;
            if (r0 < M) {
                __nv_bfloat162 p = __floats2bfloat162_rn(acc[mt][nt][0], acc[mt][nt][1]);
                *(unsigned*)(C + (size_t)r0 * HID + c) = *(unsigned*)&p;
            }
            if (r1 < M) {
                __nv_bfloat162 p = __floats2bfloat162_rn(acc[mt][nt][2], acc[mt][nt][3]);
                *(unsigned*)(C + (size_t)r1 * HID + c) = *(unsigned*)&p;
            }
        }
    }

    float* sal = (float*)smem;
    int nh = wid >> 2;
#pragma unroll
    for (int mt = 0; mt < 2; mt++) {
        float s0 = 0.f, d0 = 0.f, s1 = 0.f, d1 = 0.f;
#pragma unroll
        for (int nt = 0; nt < 8; nt++) {
            int c = wn + nt * 8 + tg * 2;
            float a0 = __ldg(&asrc[c]), a1 = __ldg(&asrc[c + 1]);
            float e0 = __ldg(&adst[c]), e1 = __ldg(&adst[c + 1]);
            s0 += acc[mt][nt][0] * a0 + acc[mt][nt][1] * a1;
            d0 += acc[mt][nt][0] * e0 + acc[mt][nt][1] * e1;
            s1 += acc[mt][nt][2] * a0 + acc[mt][nt][3] * a1;
            d1 += acc[mt][nt][2] * e0 + acc[mt][nt][3] * e1;
        }
#pragma unroll
        for (int o = 1; o <= 2; o <<= 1) {
            s0 += __shfl_xor_sync(0xffffffffu, s0, o);
            d0 += __shfl_xor_sync(0xffffffffu, d0, o);
            s1 += __shfl_xor_sync(0xffffffffu, s1, o);
            d1 += __shfl_xor_sync(0xffffffffu, d1, o);
        }
        if (tg == 0) {
            int row0 = wm + mt * 16 + gq, row1 = row0 + 8;
            sal[(row0 * 2 + nh) * 2 + 0] = s0;
            sal[(row0 * 2 + nh) * 2 + 1] = d0;
            sal[(row1 * 2 + nh) * 2 + 0] = s1;
            sal[(row1 * 2 + nh) * 2 + 1] = d1;
        }
    }
    __syncthreads();
    if (tid < 128) {
        int m = m0 + tid;
        if (m < M) {
            g_as[m] = sal[(tid * 2 + 0) * 2 + 0] + sal[(tid * 2 + 1) * 2 + 0];
            g_ad[m] = sal[(tid * 2 + 0) * 2 + 1] + sal[(tid * 2 + 1) * 2 + 1];
        }
    }
}

__global__ void __launch_bounds__(256, 2)
gemm1_kernel(const float* __restrict__ A, const float* __restrict__ W,
             __nv_bfloat16* __restrict__ C, int M,
             const float* __restrict__ asrc, const float* __restrict__ adst) {
    extern __shared__ char smem[];
    gemm_body<IND, float>(blockIdx.x, smem, A, W, C, M, asrc, adst);
}

__global__ void __launch_bounds__(256, 2)
gemm2_kernel(const __nv_bfloat16* __restrict__ A, const float* __restrict__ W,
             __nv_bfloat16* __restrict__ C, int M,
             const float* __restrict__ asrc, const float* __restrict__ adst) {
    extern __shared__ char smem[];
    gemm_body<HID, __nv_bfloat16>(blockIdx.x, smem, A, W, C, M, asrc, adst);
}

// ---------------- fused attention: warp per dst, bf16 gathers ----------------
// POOL=1 uses block-level pool reduction exploiting the SORTED batch array.
template <int POOL>
__global__ void __launch_bounds__(256)
attn_kernel(const __nv_bfloat16* __restrict__ h, const float* __restrict__ bias,
            __nv_bfloat16* __restrict__ out) {
    __shared__ float spool[8][128];
    __shared__ int   sg[8];

    int wrp = threadIdx.x >> 5;
    int d = blockIdx.x * 8 + wrp;
    int lane = threadIdx.x & 31;
    if (!POOL && d >= NN) return;
    bool valid = d < NN;

    int beg = 0, end = 0;
    float add = 0.f;
    if (valid) { beg = g_roff[d]; end = g_roff[d + 1]; add = g_ad[d]; }

    float den = 0.f;
    for (int i = beg + lane; i < end; i += 32) {
        float e = __ldg(&g_as[g_csr[i]]) + add;
        e = e > 0.f ? e : NEG_SLOPE * e;
        float w = __expf(e);
        g_w[i] = w;
        den += w;
    }
#pragma unroll
    for (int o = 16; o; o >>= 1) den += __shfl_xor_sync(0xffffffffu, den, o);
    float inv = 1.f / den;
    __syncwarp();

    float4 acc = make_float4(0.f, 0.f, 0.f, 0.f);
    int i = beg;
    for (; i + 4 <= end; i += 4) {
        int   s0 = g_csr[i],     s1 = g_csr[i + 1];
        int   s2 = g_csr[i + 2], s3 = g_csr[i + 3];
        float c0 = g_w[i] * inv,     c1 = g_w[i + 1] * inv;
        float c2 = g_w[i + 2] * inv, c3 = g_w[i + 3] * inv;
        uint2 v0 = __ldg(&((const uint2*)(h + (size_t)s0 * HID))[lane]);
        uint2 v1 = __ldg(&((const uint2*)(h + (size_t)s1 * HID))[lane]);
        uint2 v2 = __ldg(&((const uint2*)(h + (size_t)s2 * HID))[lane]);
        uint2 v3 = __ldg(&((const uint2*)(h + (size_t)s3 * HID))[lane]);
        float2 a0 = __bfloat1622float2(*(__nv_bfloat162*)&v0.x);
        float2 b0 = __bfloat1622float2(*(__nv_bfloat162*)&v0.y);
        float2 a1 = __bfloat1622float2(*(__nv_bfloat162*)&v1.x);
        float2 b1 = __bfloat1622float2(*(__nv_bfloat162*)&v1.y);
        float2 a2 = __bfloat1622float2(*(__nv_bfloat162*)&v2.x);
        float2 b2 = __bfloat1622float2(*(__nv_bfloat162*)&v2.y);
        float2 a3 = __bfloat1622float2(*(__nv_bfloat162*)&v3.x);
        float2 b3 = __bfloat1622float2(*(__nv_bfloat162*)&v3.y);
        acc.x += c0 * a0.x + c1 * a1.x + c2 * a2.x + c3 * a3.x;
        acc.y += c0 * a0.y + c1 * a1.y + c2 * a2.y + c3 * a3.y;
        acc.z += c0 * b0.x + c1 * b1.x + c2 * b2.x + c3 * b3.x;
        acc.w += c0 * b0.y + c1 * b1.y + c2 * b2.y + c3 * b3.y;
    }
    for (; i < end; i++) {
        int s = g_csr[i];
        float c = g_w[i] * inv;
        uint2 v = __ldg(&((const uint2*)(h + (size_t)s * HID))[lane]);
        float2 a = __bfloat1622float2(*(__nv_bfloat162*)&v.x);
        float2 b = __bfloat1622float2(*(__nv_bfloat162*)&v.y);
        acc.x += c * a.x; acc.y += c * a.y;
        acc.z += c * b.x; acc.w += c * b.y;
    }

    float4 bb = ((const float4*)bias)[lane];
    acc.x = fmaxf(acc.x + bb.x, 0.f);
    acc.y = fmaxf(acc.y + bb.y, 0.f);
    acc.z = fmaxf(acc.z + bb.z, 0.f);
    acc.w = fmaxf(acc.w + bb.w, 0.f);

    if (!POOL) {
        __nv_bfloat162 o0 = __floats2bfloat162_rn(acc.x, acc.y);
        __nv_bfloat162 o1 = __floats2bfloat162_rn(acc.z, acc.w);
        uint2 pk;
        pk.x = *(unsigned*)&o0; pk.y = *(unsigned*)&o1;
        ((uint2*)(out + (size_t)d * HID))[lane] = pk;
    } else {
        *(float4*)(&spool[wrp][lane * 4]) = acc;
        if (lane == 0) sg[wrp] = valid ? g_batch[d] : -1;
        __syncthreads();
        int t = threadIdx.x;
        if (t < 128) {
            float accq = 0.f;
            int curg = -1;
#pragma unroll
            for (int r = 0; r < 8; r++) {
                int g = sg[r];
                if (g < 0) break;          // invalid rows trail (d monotonic)
                if (g != curg) {
                    if (curg >= 0) atomicAdd(&g_pool[curg * HID + t], accq);
                    curg = g;
                    accq = 0.f;
                }
                accq += spool[r][t];
            }
            if (curg >= 0) atomicAdd(&g_pool[curg * HID + t], accq);
        }
    }
}

// ---------------- classifier head (also re-zeroes pool/gcnt for next replay) ----------------
__global__ void head_kernel(const float* __restrict__ Wc,
                            const float* __restrict__ bc,
                            float* __restrict__ out) {
    __shared__ float ssum[4];
    int g = blockIdx.x;
    int t = threadIdx.x;         // 128 threads
    int lane = t & 31, wrp = t >> 5;
    float s = g_pool[g * HID + t] * __ldg(&Wc[t]);
#pragma unroll
    for (int o = 16; o; o >>= 1) s += __shfl_xor_sync(0xffffffffu, s, o);
    if (lane == 0) ssum[wrp] = s;
    __syncthreads();
    if (t == 0) {
        float tot = ssum[0] + ssum[1] + ssum[2] + ssum[3];
        float c = fmaxf((float)g_gcnt[g], 1.f);
        float v = tot / c + bc[0];
        out[g] = 1.f / (1.f + expf(-v));
    }
    g_pool[g * HID + t] = 0.f;
    if (t == 0) g_gcnt[g] = 0;
}

// ---------------- launch ----------------
extern "C" void kernel_launch(void* const* d_in, const int* in_sizes, int n_in,
                              void* d_out, int out_size) {
    const float* x    = (const float*)d_in[0];
    const void*  edge = d_in[1];
    const void*  batch= d_in[2];
    const float* W1   = (const float*)d_in[3];
    const float* as1  = (const float*)d_in[4];
    const float* ad1  = (const float*)d_in[5];
    const float* b1   = (const float*)d_in[6];
    const float* W2   = (const float*)d_in[7];
    const float* as2  = (const float*)d_in[8];
    const float* ad2  = (const float*)d_in[9];
    const float* b2   = (const float*)d_in[10];
    const float* Wc   = (const float*)d_in[11];
    const float* bc   = (const float*)d_in[12];
    float* out = (float*)d_out;
    (void)in_sizes; (void)n_in; (void)out_size;

    __nv_bfloat16* hb;  cudaGetSymbolAddress((void**)&hb,  g_hb);
    __nv_bfloat16* hb2; cudaGetSymbolAddress((void**)&hb2, g_hb2);

    const int HB = (NE + 255) / 256;
    const int WB = (NN + 7) / 8;

    const int SMEM = 2 * 128 * 136 * 2;   // 69632
    cudaFuncSetAttribute(gemm1_kernel,
                         cudaFuncAttributeMaxDynamicSharedMemorySize, SMEM);
    cudaFuncSetAttribute(gemm2_kernel,
                         cudaFuncAttributeMaxDynamicSharedMemorySize, SMEM);

    hist_kernel<<<HB, 256>>>(edge, batch);                            // 1
    scan_kernel<<<SCAN_B, 256>>>();                                   // 2
    fill_kernel<<<FILL_B, 256>>>(edge);                               // 3
    gemm1_kernel<<<GEMM_B, 256, SMEM>>>(x, W1, hb, NN, as1, ad1);     // 4: profiled? (gemm1)
    attn_kernel<0><<<WB, 256>>>(hb, b1, hb2);                         // 5
    gemm2_kernel<<<GEMM_B, 256, SMEM>>>(hb2, W2, hb, NN, as2, ad2);   // 6
    attn_kernel<1><<<WB, 256>>>(hb, b2, nullptr);                     // 7
    head_kernel<<<NG, 128>>>(Wc, bc, out);                            // 8
}